// round 9
// baseline (speedup 1.0000x reference)
#include <cuda_runtime.h>

#define NN 50000
#define EE 800000
#define FDIM 128
#define NBLK 49  // ceil(NN/1024)

typedef unsigned long long ull;

// ---------------- scratch (device globals; no allocation) ----------------
__device__ float g_xl[NN * FDIM];
__device__ float g_xr[NN * FDIM];
__device__ float g_h[NN * FDIM];
__device__ int g_counts[NN];
__device__ int g_rowptr[NN + 1];
__device__ int g_next[NN];
__device__ int g_src[EE];
__device__ int g_is64;
__device__ int g_blksum[64];
__device__ int g_blkoff[64];

// ---------------- side stream + fork/join events ----------------
struct SideStream {
    cudaStream_t s2;
    cudaEvent_t e1, e2;
    SideStream() {
        cudaStreamCreateWithFlags(&s2, cudaStreamNonBlocking);
        cudaEventCreateWithFlags(&e1, cudaEventDisableTiming);
        cudaEventCreateWithFlags(&e2, cudaEventDisableTiming);
    }
};
static SideStream g_ss;

// ---------------- f32x2 packed-FMA helpers (SASS FFMA2; PTX-only path) ----------------
__device__ __forceinline__ void fma2(ull& d, ull a, ull b) {
    asm("fma.rn.f32x2 %0, %1, %2, %0;" : "+l"(d) : "l"(a), "l"(b));
}
__device__ __forceinline__ float2 unpack2(ull v) {
    float2 f;
    asm("mov.b64 {%0, %1}, %2;" : "=f"(f.x), "=f"(f.y) : "l"(v));
    return f;
}

// ---------------- detect dtype (int32 vs int64) + zero counts ----------------
__global__ void k_detect_zero(const unsigned int* __restrict__ w) {
    int i = blockIdx.x * 256 + threadIdx.x;
    if (i < NN) g_counts[i] = 0;
    if (blockIdx.x == 0) {
        __shared__ int cnt;
        if (threadIdx.x == 0) cnt = 0;
        __syncthreads();
        int z = 0;
        for (int k = threadIdx.x; k < 1024; k += 256)
            if (w[2 * k + 1] == 0u) z++;
        atomicAdd(&cnt, z);
        __syncthreads();
        if (threadIdx.x == 0) g_is64 = (cnt > 512) ? 1 : 0;
    }
}

__device__ __forceinline__ int load_idx(const void* ei, long pos) {
    return g_is64 ? (int)((const long long*)ei)[pos] : ((const int*)ei)[pos];
}

// ---------------- CSR build ----------------
__global__ void k_hist(const void* __restrict__ ei) {
    int e = blockIdx.x * blockDim.x + threadIdx.x;
    if (e < EE) atomicAdd(&g_counts[load_idx(ei, (long)EE + e)], 1);
}

__global__ void k_scan_block() {
    __shared__ int wsum[32];
    int i = blockIdx.x * 1024 + threadIdx.x;
    int lane = threadIdx.x & 31, wid = threadIdx.x >> 5;
    int v = (i < NN) ? g_counts[i] : 0;
    int incl = v;
#pragma unroll
    for (int o = 1; o < 32; o <<= 1) {
        int xx = __shfl_up_sync(0xffffffffu, incl, o);
        if (lane >= o) incl += xx;
    }
    if (lane == 31) wsum[wid] = incl;
    __syncthreads();
    if (wid == 0) {
        int ws = wsum[lane];
        int wincl = ws;
#pragma unroll
        for (int o = 1; o < 32; o <<= 1) {
            int xx = __shfl_up_sync(0xffffffffu, wincl, o);
            if (lane >= o) wincl += xx;
        }
        wsum[lane] = wincl - ws;
    }
    __syncthreads();
    int excl = wsum[wid] + incl - v;
    if (i < NN) g_rowptr[i] = excl;
    if (threadIdx.x == 1023) g_blksum[blockIdx.x] = excl + v;
}

__global__ void k_scan_tops() {
    int lane = threadIdx.x;
    int v0 = (2 * lane < NBLK) ? g_blksum[2 * lane] : 0;
    int v1 = (2 * lane + 1 < NBLK) ? g_blksum[2 * lane + 1] : 0;
    int s = v0 + v1;
    int incl = s;
#pragma unroll
    for (int o = 1; o < 32; o <<= 1) {
        int xx = __shfl_up_sync(0xffffffffu, incl, o);
        if (lane >= o) incl += xx;
    }
    int excl = incl - s;
    if (2 * lane < NBLK) g_blkoff[2 * lane] = excl;
    if (2 * lane + 1 < NBLK) g_blkoff[2 * lane + 1] = excl + v0;
    if (lane == 31) g_rowptr[NN] = incl;
}

__global__ void k_scan_add() {
    int i = blockIdx.x * 1024 + threadIdx.x;
    if (i < NN) {
        int r = g_rowptr[i] + g_blkoff[blockIdx.x];
        g_rowptr[i] = r;
        g_next[i] = r;
    }
}

__global__ void k_scatter(const void* __restrict__ ei) {
    int e = blockIdx.x * blockDim.x + threadIdx.x;
    if (e < EE) {
        int dn = load_idx(ei, (long)EE + e);
        int sn = load_idx(ei, e);
        int pos = atomicAdd(&g_next[dn], 1);
        g_src[pos] = sn;
    }
}

// ---------------- dual GEMM: g_xl = A@W1, g_xr = A@W2  (M=NN, K=N=128) ----------------
// 64x256 block tile, 256 threads, 2 CTAs/SM, double-buffered smem,
// 8x8 micro-tile via f32x2 packed FMA, A stored DUPLICATED (zero pack MOVs).
template <bool USE_H>
__global__ void __launch_bounds__(256, 2)
k_dual_gemm(const float* __restrict__ A_param,
            const float* __restrict__ W1, const float* __restrict__ W2) {
    const float* A = USE_H ? (const float*)g_h : A_param;
    __shared__ float As2[2][16][128];  // [buf][k][2r(+dup)] : 16KB
    __shared__ float Ws[2][16][256];   // [buf][k][col]      : 32KB
    int t = threadIdx.x;
    int row0 = blockIdx.x * 64;
    int wid = t >> 5, ct = t & 31;     // warp -> 8 rows, lane -> 4+4 cols
    int ar = t >> 2, ac = t & 3;       // A-load: row 0..63, k-quad 0..3
    int gr = row0 + ar;

    ull acc2[8][4];
#pragma unroll
    for (int i = 0; i < 8; i++)
#pragma unroll
        for (int j = 0; j < 4; j++) acc2[i][j] = 0ull;

    float4 aT, wT[4];
    // prologue: load chunk 0
    aT = (gr < NN) ? *(const float4*)(A + (long)gr * FDIM + ac * 4)
                   : make_float4(0.f, 0.f, 0.f, 0.f);
#pragma unroll
    for (int i = 0; i < 4; i++) {
        int idx = t + i * 256;
        int k = idx >> 6, c4 = idx & 63;
        wT[i] = (c4 < 32) ? *(const float4*)(W1 + k * FDIM + c4 * 4)
                          : *(const float4*)(W2 + k * FDIM + (c4 - 32) * 4);
    }
    // store chunk 0 into buf 0
    {
        float av[4] = {aT.x, aT.y, aT.z, aT.w};
#pragma unroll
        for (int j = 0; j < 4; j++)
            *(float2*)(&As2[0][ac * 4 + j][2 * ar]) = make_float2(av[j], av[j]);
#pragma unroll
        for (int i = 0; i < 4; i++) {
            int idx = t + i * 256;
            int k = idx >> 6, c4 = idx & 63;
            *(float4*)(&Ws[0][k][c4 * 4]) = wT[i];
        }
    }
    __syncthreads();

#pragma unroll
    for (int c = 0; c < 8; c++) {
        int buf = c & 1;
        // prefetch chunk c+1 into registers
        if (c < 7) {
            int kn = (c + 1) * 16;
            aT = (gr < NN) ? *(const float4*)(A + (long)gr * FDIM + kn + ac * 4)
                           : make_float4(0.f, 0.f, 0.f, 0.f);
#pragma unroll
            for (int i = 0; i < 4; i++) {
                int idx = t + i * 256;
                int k = idx >> 6, c4 = idx & 63;
                wT[i] = (c4 < 32) ? *(const float4*)(W1 + (kn + k) * FDIM + c4 * 4)
                                  : *(const float4*)(W2 + (kn + k) * FDIM + (c4 - 32) * 4);
            }
        }

        // compute from buf
#pragma unroll 8
        for (int kk = 0; kk < 16; kk++) {
            ulonglong2 aD0 = *(const ulonglong2*)(&As2[buf][kk][wid * 16]);
            ulonglong2 aD1 = *(const ulonglong2*)(&As2[buf][kk][wid * 16 + 4]);
            ulonglong2 aD2 = *(const ulonglong2*)(&As2[buf][kk][wid * 16 + 8]);
            ulonglong2 aD3 = *(const ulonglong2*)(&As2[buf][kk][wid * 16 + 12]);
            ulonglong2 w01 = *(const ulonglong2*)(&Ws[buf][kk][ct * 4]);
            ulonglong2 w23 = *(const ulonglong2*)(&Ws[buf][kk][ct * 4 + 128]);
            ull ad[8] = {aD0.x, aD0.y, aD1.x, aD1.y, aD2.x, aD2.y, aD3.x, aD3.y};
#pragma unroll
            for (int i = 0; i < 8; i++) {
                fma2(acc2[i][0], ad[i], w01.x);
                fma2(acc2[i][1], ad[i], w01.y);
                fma2(acc2[i][2], ad[i], w23.x);
                fma2(acc2[i][3], ad[i], w23.y);
            }
        }

        // store prefetched chunk into the other buffer
        if (c < 7) {
            int nb = buf ^ 1;
            float av[4] = {aT.x, aT.y, aT.z, aT.w};
#pragma unroll
            for (int j = 0; j < 4; j++)
                *(float2*)(&As2[nb][ac * 4 + j][2 * ar]) = make_float2(av[j], av[j]);
#pragma unroll
            for (int i = 0; i < 4; i++) {
                int idx = t + i * 256;
                int k = idx >> 6, c4 = idx & 63;
                *(float4*)(&Ws[nb][k][c4 * 4]) = wT[i];
            }
        }
        __syncthreads();
    }

#pragma unroll
    for (int i = 0; i < 8; i++) {
        int gr2 = row0 + wid * 8 + i;
        if (gr2 < NN) {
            float2 p0 = unpack2(acc2[i][0]), p1 = unpack2(acc2[i][1]);
            float2 p2 = unpack2(acc2[i][2]), p3 = unpack2(acc2[i][3]);
            *(float4*)(g_xl + (long)gr2 * FDIM + ct * 4) =
                make_float4(p0.x, p0.y, p1.x, p1.y);
            *(float4*)(g_xr + (long)gr2 * FDIM + ct * 4) =
                make_float4(p2.x, p2.y, p3.x, p3.y);
        }
    }
}

// ---------------- fused per-node attention (online softmax), warp per node ----------------
__device__ __forceinline__ float lrelu(float v) { return v > 0.f ? v : 0.2f * v; }

template <int H, bool OUT_H>
__global__ void k_aggregate(const float* __restrict__ att, const float* __restrict__ bias,
                            float* __restrict__ out_param) {
    float* out = OUT_H ? (float*)g_h : out_param;
    int gw = (blockIdx.x * blockDim.x + threadIdx.x) >> 5;
    int lane = threadIdx.x & 31;
    if (gw >= NN) return;
    int n = gw;

    float4 xrv = *(const float4*)(g_xr + (long)n * FDIM + lane * 4);
    float4 av  = *(const float4*)(att + lane * 4);
    float4 bv  = *(const float4*)(bias + lane * 4);

    // self-loop first: bootstraps m/d/acc, no -inf handling
    float4 xlv = *(const float4*)(g_xl + (long)n * FDIM + lane * 4);
    float p = lrelu(xlv.x + xrv.x) * av.x
            + lrelu(xlv.y + xrv.y) * av.y
            + lrelu(xlv.z + xrv.z) * av.z
            + lrelu(xlv.w + xrv.w) * av.w;
#pragma unroll
    for (int o = 1; o < 32 / H; o <<= 1)
        p += __shfl_xor_sync(0xffffffffu, p, o);
    float m = p;
    float d = 1.f;
    float4 acc = xlv;

    int start = g_rowptr[n], end = g_rowptr[n + 1];
    for (int j = start; j < end; j++) {
        int s = g_src[j];
        xlv = *(const float4*)(g_xl + (long)s * FDIM + lane * 4);
        p = lrelu(xlv.x + xrv.x) * av.x
          + lrelu(xlv.y + xrv.y) * av.y
          + lrelu(xlv.z + xrv.z) * av.z
          + lrelu(xlv.w + xrv.w) * av.w;
#pragma unroll
        for (int o = 1; o < 32 / H; o <<= 1)
            p += __shfl_xor_sync(0xffffffffu, p, o);
        if (p > m) {
            float sc = __expf(m - p);
            d = fmaf(d, sc, 1.f);
            acc.x = fmaf(acc.x, sc, xlv.x);
            acc.y = fmaf(acc.y, sc, xlv.y);
            acc.z = fmaf(acc.z, sc, xlv.z);
            acc.w = fmaf(acc.w, sc, xlv.w);
            m = p;
        } else {
            float pe = __expf(p - m);
            d += pe;
            acc.x = fmaf(pe, xlv.x, acc.x);
            acc.y = fmaf(pe, xlv.y, acc.y);
            acc.z = fmaf(pe, xlv.z, acc.z);
            acc.w = fmaf(pe, xlv.w, acc.w);
        }
    }
    float inv = 1.f / d;
    float4 o = make_float4(fmaf(acc.x, inv, bv.x), fmaf(acc.y, inv, bv.y),
                           fmaf(acc.z, inv, bv.z), fmaf(acc.w, inv, bv.w));
    *(float4*)(out + (long)n * FDIM + lane * 4) = o;
}

// ---------------- launch ----------------
extern "C" void kernel_launch(void* const* d_in, const int* in_sizes, int n_in,
                              void* d_out, int out_size) {
    const float* x    = (const float*)d_in[0];
    const void*  ei   = d_in[1];
    const float* Wl1  = (const float*)d_in[3];
    const float* Wr1  = (const float*)d_in[4];
    const float* att1 = (const float*)d_in[5];
    const float* b1   = (const float*)d_in[6];
    const float* Wl2  = (const float*)d_in[7];
    const float* Wr2  = (const float*)d_in[8];
    const float* att2 = (const float*)d_in[9];
    const float* b2   = (const float*)d_in[10];
    float* out = (float*)d_out;

    int gemm_blocks = (NN + 63) / 64;
    int agg_blocks = (NN + 7) / 8;
    cudaStream_t s2 = g_ss.s2;

    // fork: CSR build on s2, overlapping the layer-1 GEMM (incl. its tail wave)
    cudaEventRecord(g_ss.e1, 0);
    cudaStreamWaitEvent(s2, g_ss.e1, 0);

    k_detect_zero<<<(NN + 255) / 256, 256, 0, s2>>>((const unsigned int*)ei);
    k_hist<<<(EE + 255) / 256, 256, 0, s2>>>(ei);
    k_scan_block<<<NBLK, 1024, 0, s2>>>();
    k_scan_tops<<<1, 32, 0, s2>>>();
    k_scan_add<<<NBLK, 1024, 0, s2>>>();
    k_scatter<<<(EE + 255) / 256, 256, 0, s2>>>(ei);
    cudaEventRecord(g_ss.e2, s2);

    k_dual_gemm<false><<<gemm_blocks, 256>>>(x, Wl1, Wr1);

    // join
    cudaStreamWaitEvent(0, g_ss.e2, 0);

    k_aggregate<2, true><<<agg_blocks, 256>>>(att1, b1, nullptr);
    k_dual_gemm<true><<<gemm_blocks, 256>>>(nullptr, Wl2, Wr2);
    k_aggregate<1, false><<<agg_blocks, 256>>>(att2, b2, out);
}

// round 10
// speedup vs baseline: 1.1244x; 1.1244x over previous
#include <cuda_runtime.h>

#define NN 50000
#define EE 800000
#define FDIM 128
#define NBLK 49  // ceil(NN/1024)

typedef unsigned long long ull;

// ---------------- scratch (device globals; no allocation) ----------------
__device__ float g_xl[NN * FDIM];
__device__ float g_xr[NN * FDIM];
__device__ float g_h[NN * FDIM];
__device__ int g_counts[NN];
__device__ int g_rowptr[NN + 1];
__device__ int g_next[NN];
__device__ int g_src[EE];
__device__ int g_is64;
__device__ int g_blksum[64];
__device__ int g_flagarr[64];

// ---------------- f32x2 packed-FMA helpers (SASS FFMA2; PTX-only path) ----------------
__device__ __forceinline__ ull pack2(float x, float y) {
    ull r;
    asm("mov.b64 %0, {%1, %2};" : "=l"(r) : "f"(x), "f"(y));
    return r;
}
__device__ __forceinline__ void fma2(ull& d, ull a, ull b) {
    asm("fma.rn.f32x2 %0, %1, %2, %0;" : "+l"(d) : "l"(a), "l"(b));
}
__device__ __forceinline__ float2 unpack2(ull v) {
    float2 f;
    asm("mov.b64 {%0, %1}, %2;" : "=f"(f.x), "=f"(f.y) : "l"(v));
    return f;
}

// ---------------- detect dtype + zero counts + zero flags ----------------
__global__ void k_detect_zero(const unsigned int* __restrict__ w) {
    int i = blockIdx.x * 256 + threadIdx.x;
    if (i < NN) g_counts[i] = 0;
    if (blockIdx.x == 1 && threadIdx.x < 64) g_flagarr[threadIdx.x] = 0;
    if (blockIdx.x == 0) {
        __shared__ int cnt;
        if (threadIdx.x == 0) cnt = 0;
        __syncthreads();
        int z = 0;
        for (int k = threadIdx.x; k < 1024; k += 256)
            if (w[2 * k + 1] == 0u) z++;
        atomicAdd(&cnt, z);
        __syncthreads();
        if (threadIdx.x == 0) g_is64 = (cnt > 512) ? 1 : 0;
    }
}

__device__ __forceinline__ int load_idx(const void* ei, long pos) {
    return g_is64 ? (int)((const long long*)ei)[pos] : ((const int*)ei)[pos];
}

// ---------------- CSR build ----------------
__global__ void k_hist(const void* __restrict__ ei) {
    int e = blockIdx.x * blockDim.x + threadIdx.x;
    if (e < EE) atomicAdd(&g_counts[load_idx(ei, (long)EE + e)], 1);
}

// single-kernel scan: per-block scan + decoupled aggregate exchange.
// All NBLK=49 blocks are co-resident (<< 148 SMs) so flag-spin cannot deadlock.
__global__ void k_scan_fused() {
    __shared__ int wsum[32];
    __shared__ int s_total, s_off;
    int bid = blockIdx.x;
    int i = bid * 1024 + threadIdx.x;
    int lane = threadIdx.x & 31, wid = threadIdx.x >> 5;
    int v = (i < NN) ? g_counts[i] : 0;
    int incl = v;
#pragma unroll
    for (int o = 1; o < 32; o <<= 1) {
        int xx = __shfl_up_sync(0xffffffffu, incl, o);
        if (lane >= o) incl += xx;
    }
    if (lane == 31) wsum[wid] = incl;
    __syncthreads();
    if (wid == 0) {
        int ws = wsum[lane];
        int wincl = ws;
#pragma unroll
        for (int o = 1; o < 32; o <<= 1) {
            int xx = __shfl_up_sync(0xffffffffu, wincl, o);
            if (lane >= o) wincl += xx;
        }
        wsum[lane] = wincl - ws;  // exclusive warp offsets
        if (lane == 31) s_total = wincl;
    }
    __syncthreads();
    int excl = wsum[wid] + incl - v;

    // publish this block's aggregate, then sum predecessors' aggregates
    if (threadIdx.x == 0) {
        g_blksum[bid] = s_total;
        __threadfence();
        atomicExch(&g_flagarr[bid], 1);
    }
    if (wid == 0) {
        int sum = 0;
        for (int p = lane; p < bid; p += 32) {
            while (atomicAdd(&g_flagarr[p], 0) == 0) {}
            sum += g_blksum[p];
        }
#pragma unroll
        for (int o = 16; o > 0; o >>= 1)
            sum += __shfl_xor_sync(0xffffffffu, sum, o);
        if (lane == 0) s_off = sum;
    }
    __syncthreads();
    if (i < NN) {
        int r = excl + s_off;
        g_rowptr[i] = r;
        g_next[i] = r;
    }
    if (bid == 0 && threadIdx.x == 0) g_rowptr[NN] = EE;  // total is a constant
}

__global__ void k_scatter(const void* __restrict__ ei) {
    int e = blockIdx.x * blockDim.x + threadIdx.x;
    if (e < EE) {
        int dn = load_idx(ei, (long)EE + e);
        int sn = load_idx(ei, e);
        int pos = atomicAdd(&g_next[dn], 1);
        g_src[pos] = sn;
    }
}

// ---------------- dual GEMM (best measured config: 80.9us) ----------------
// 128x256 block tile, 512 threads, 8x8 micro-tile via f32x2 packed FMA,
// software-pipelined global->smem loads.
template <bool USE_H>
__global__ void __launch_bounds__(512, 1)
k_dual_gemm(const float* __restrict__ A_param,
            const float* __restrict__ W1, const float* __restrict__ W2) {
    const float* A = USE_H ? (const float*)g_h : A_param;
    __shared__ float As[32][128];   // As[k][row] (transposed chunk)
    __shared__ float Ws[32][256];   // Ws[k][col] (W1 | W2)
    int t = threadIdx.x;
    int row0 = blockIdx.x * 128;
    int rt = t >> 5, ct = t & 31;

    int ar0 = t >> 3, ac0 = t & 7;
    int ar1 = (t + 512) >> 3, ac1 = (t + 512) & 7;
    int gr0 = row0 + ar0, gr1 = row0 + ar1;

    ull acc2[8][4];
#pragma unroll
    for (int i = 0; i < 8; i++)
#pragma unroll
        for (int j = 0; j < 4; j++) acc2[i][j] = 0ull;

    float4 aT[2], wT[4];
    aT[0] = (gr0 < NN) ? *(const float4*)(A + (long)gr0 * FDIM + ac0 * 4)
                       : make_float4(0.f, 0.f, 0.f, 0.f);
    aT[1] = (gr1 < NN) ? *(const float4*)(A + (long)gr1 * FDIM + ac1 * 4)
                       : make_float4(0.f, 0.f, 0.f, 0.f);
#pragma unroll
    for (int i = 0; i < 4; i++) {
        int idx = t + i * 512;
        int k = idx >> 6, c4 = idx & 63;
        wT[i] = (c4 < 32) ? *(const float4*)(W1 + k * FDIM + c4 * 4)
                          : *(const float4*)(W2 + k * FDIM + (c4 - 32) * 4);
    }

    for (int kc = 0; kc < 128; kc += 32) {
        As[ac0 * 4 + 0][ar0] = aT[0].x;
        As[ac0 * 4 + 1][ar0] = aT[0].y;
        As[ac0 * 4 + 2][ar0] = aT[0].z;
        As[ac0 * 4 + 3][ar0] = aT[0].w;
        As[ac1 * 4 + 0][ar1] = aT[1].x;
        As[ac1 * 4 + 1][ar1] = aT[1].y;
        As[ac1 * 4 + 2][ar1] = aT[1].z;
        As[ac1 * 4 + 3][ar1] = aT[1].w;
#pragma unroll
        for (int i = 0; i < 4; i++) {
            int idx = t + i * 512;
            int k = idx >> 6, c4 = idx & 63;
            *(float4*)(&Ws[k][c4 * 4]) = wT[i];
        }
        __syncthreads();

        int kn = kc + 32;
        if (kn < 128) {
            aT[0] = (gr0 < NN) ? *(const float4*)(A + (long)gr0 * FDIM + kn + ac0 * 4)
                               : make_float4(0.f, 0.f, 0.f, 0.f);
            aT[1] = (gr1 < NN) ? *(const float4*)(A + (long)gr1 * FDIM + kn + ac1 * 4)
                               : make_float4(0.f, 0.f, 0.f, 0.f);
#pragma unroll
            for (int i = 0; i < 4; i++) {
                int idx = t + i * 512;
                int k = idx >> 6, c4 = idx & 63;
                wT[i] = (c4 < 32) ? *(const float4*)(W1 + (kn + k) * FDIM + c4 * 4)
                                  : *(const float4*)(W2 + (kn + k) * FDIM + (c4 - 32) * 4);
            }
        }

#pragma unroll 4
        for (int kk = 0; kk < 32; kk++) {
            float4 a0 = *(const float4*)(&As[kk][rt * 8]);
            float4 a1 = *(const float4*)(&As[kk][rt * 8 + 4]);
            ulonglong2 w01 = *(const ulonglong2*)(&Ws[kk][ct * 4]);
            ulonglong2 w23 = *(const ulonglong2*)(&Ws[kk][ct * 4 + 128]);
            float a[8] = {a0.x, a0.y, a0.z, a0.w, a1.x, a1.y, a1.z, a1.w};
#pragma unroll
            for (int i = 0; i < 8; i++) {
                ull ap = pack2(a[i], a[i]);
                fma2(acc2[i][0], ap, w01.x);
                fma2(acc2[i][1], ap, w01.y);
                fma2(acc2[i][2], ap, w23.x);
                fma2(acc2[i][3], ap, w23.y);
            }
        }
        __syncthreads();
    }

#pragma unroll
    for (int i = 0; i < 8; i++) {
        int gr = row0 + rt * 8 + i;
        if (gr < NN) {
            float2 p0 = unpack2(acc2[i][0]), p1 = unpack2(acc2[i][1]);
            float2 p2 = unpack2(acc2[i][2]), p3 = unpack2(acc2[i][3]);
            *(float4*)(g_xl + (long)gr * FDIM + ct * 4) =
                make_float4(p0.x, p0.y, p1.x, p1.y);
            *(float4*)(g_xr + (long)gr * FDIM + ct * 4) =
                make_float4(p2.x, p2.y, p3.x, p3.y);
        }
    }
}

// ---------------- fused per-node attention (online softmax), warp per node ----------------
__device__ __forceinline__ float lrelu(float v) { return v > 0.f ? v : 0.2f * v; }

template <int H>
__device__ __forceinline__ float edge_score(float4 xlv, float4 xrv, float4 av, int lane) {
    float p = lrelu(xlv.x + xrv.x) * av.x
            + lrelu(xlv.y + xrv.y) * av.y
            + lrelu(xlv.z + xrv.z) * av.z
            + lrelu(xlv.w + xrv.w) * av.w;
#pragma unroll
    for (int o = 1; o < 32 / H; o <<= 1)
        p += __shfl_xor_sync(0xffffffffu, p, o);
    return p;
}

template <int H, bool OUT_H>
__global__ void k_aggregate(const float* __restrict__ att, const float* __restrict__ bias,
                            float* __restrict__ out_param) {
    float* out = OUT_H ? (float*)g_h : out_param;
    int gw = (blockIdx.x * blockDim.x + threadIdx.x) >> 5;
    int lane = threadIdx.x & 31;
    if (gw >= NN) return;
    int n = gw;

    float4 xrv = *(const float4*)(g_xr + (long)n * FDIM + lane * 4);
    float4 av  = *(const float4*)(att + lane * 4);
    float4 bv  = *(const float4*)(bias + lane * 4);

    // self-loop first: bootstraps m/d/acc
    float4 x1 = *(const float4*)(g_xl + (long)n * FDIM + lane * 4);
    float m = edge_score<H>(x1, xrv, av, lane);
    float d = 1.f;
    float4 acc = x1;

    int j = g_rowptr[n], end = g_rowptr[n + 1];
    // 2-edge unrolled main loop: two independent gathers in flight
    for (; j + 1 < end; j += 2) {
        int s1 = g_src[j], s2 = g_src[j + 1];
        x1 = *(const float4*)(g_xl + (long)s1 * FDIM + lane * 4);
        float4 x2 = *(const float4*)(g_xl + (long)s2 * FDIM + lane * 4);
        float p1 = edge_score<H>(x1, xrv, av, lane);
        float p2 = edge_score<H>(x2, xrv, av, lane);
        float pm = fmaxf(p1, p2);
        if (pm <= m) {
            float e1 = __expf(p1 - m), e2 = __expf(p2 - m);
            d += e1 + e2;
            acc.x = fmaf(e1, x1.x, fmaf(e2, x2.x, acc.x));
            acc.y = fmaf(e1, x1.y, fmaf(e2, x2.y, acc.y));
            acc.z = fmaf(e1, x1.z, fmaf(e2, x2.z, acc.z));
            acc.w = fmaf(e1, x1.w, fmaf(e2, x2.w, acc.w));
        } else {
            float sc = __expf(m - pm);
            float e1 = __expf(p1 - pm), e2 = __expf(p2 - pm);
            d = fmaf(d, sc, e1 + e2);
            acc.x = fmaf(acc.x, sc, fmaf(e1, x1.x, e2 * x2.x));
            acc.y = fmaf(acc.y, sc, fmaf(e1, x1.y, e2 * x2.y));
            acc.z = fmaf(acc.z, sc, fmaf(e1, x1.z, e2 * x2.z));
            acc.w = fmaf(acc.w, sc, fmaf(e1, x1.w, e2 * x2.w));
            m = pm;
        }
    }
    // tail edge
    if (j < end) {
        int s1 = g_src[j];
        x1 = *(const float4*)(g_xl + (long)s1 * FDIM + lane * 4);
        float p1 = edge_score<H>(x1, xrv, av, lane);
        if (p1 <= m) {
            float e1 = __expf(p1 - m);
            d += e1;
            acc.x = fmaf(e1, x1.x, acc.x);
            acc.y = fmaf(e1, x1.y, acc.y);
            acc.z = fmaf(e1, x1.z, acc.z);
            acc.w = fmaf(e1, x1.w, acc.w);
        } else {
            float sc = __expf(m - p1);
            d = fmaf(d, sc, 1.f);
            acc.x = fmaf(acc.x, sc, x1.x);
            acc.y = fmaf(acc.y, sc, x1.y);
            acc.z = fmaf(acc.z, sc, x1.z);
            acc.w = fmaf(acc.w, sc, x1.w);
        }
    }
    float inv = 1.f / d;
    float4 o = make_float4(fmaf(acc.x, inv, bv.x), fmaf(acc.y, inv, bv.y),
                           fmaf(acc.z, inv, bv.z), fmaf(acc.w, inv, bv.w));
    *(float4*)(out + (long)n * FDIM + lane * 4) = o;
}

// ---------------- launch: kernel launches ONLY ----------------
extern "C" void kernel_launch(void* const* d_in, const int* in_sizes, int n_in,
                              void* d_out, int out_size) {
    const float* x    = (const float*)d_in[0];
    const void*  ei   = d_in[1];
    const float* Wl1  = (const float*)d_in[3];
    const float* Wr1  = (const float*)d_in[4];
    const float* att1 = (const float*)d_in[5];
    const float* b1   = (const float*)d_in[6];
    const float* Wl2  = (const float*)d_in[7];
    const float* Wr2  = (const float*)d_in[8];
    const float* att2 = (const float*)d_in[9];
    const float* b2   = (const float*)d_in[10];
    float* out = (float*)d_out;

    int gemm_blocks = (NN + 127) / 128;
    int agg_blocks = (NN + 7) / 8;

    k_detect_zero<<<(NN + 255) / 256, 256>>>((const unsigned int*)ei);  // 0
    k_hist<<<(EE + 255) / 256, 256>>>(ei);                              // 1
    k_scan_fused<<<NBLK, 1024>>>();                                     // 2
    k_scatter<<<(EE + 255) / 256, 256>>>(ei);                           // 3
    k_dual_gemm<false><<<gemm_blocks, 512>>>(x, Wl1, Wr1);              // 4
    k_aggregate<2, true><<<agg_blocks, 256>>>(att1, b1, nullptr);       // 5 (profiled)
    k_dual_gemm<true><<<gemm_blocks, 512>>>(nullptr, Wl2, Wr2);         // 6
    k_aggregate<1, false><<<agg_blocks, 256>>>(att2, b2, out);          // 7
}

// round 11
// speedup vs baseline: 1.1982x; 1.0656x over previous
#include <cuda_runtime.h>

#define NN 50000
#define EE 800000
#define FDIM 128
#define NBLK 49  // ceil(NN/1024)

typedef unsigned long long ull;

// ---------------- scratch (device globals; no allocation) ----------------
__device__ float g_xl[NN * FDIM];
__device__ float g_xr[NN * FDIM];
__device__ float g_h[NN * FDIM];
__device__ int g_counts[NN];
__device__ int g_rowptr[NN + 1];
__device__ int g_next[NN];
__device__ int g_src[EE];
__device__ int g_is64;
__device__ int g_blksum[64];
__device__ int g_flagarr[64];

// ---------------- side stream + fork/join events ----------------
struct SideStream {
    cudaStream_t s2;
    cudaEvent_t e1, e2;
    SideStream() {
        cudaStreamCreateWithFlags(&s2, cudaStreamNonBlocking);
        cudaEventCreateWithFlags(&e1, cudaEventDisableTiming);
        cudaEventCreateWithFlags(&e2, cudaEventDisableTiming);
    }
};
static SideStream g_ss;

// ---------------- f32x2 packed-FMA helpers (SASS FFMA2; PTX-only path) ----------------
__device__ __forceinline__ ull pack2(float x, float y) {
    ull r;
    asm("mov.b64 %0, {%1, %2};" : "=l"(r) : "f"(x), "f"(y));
    return r;
}
__device__ __forceinline__ void fma2(ull& d, ull a, ull b) {
    asm("fma.rn.f32x2 %0, %1, %2, %0;" : "+l"(d) : "l"(a), "l"(b));
}
__device__ __forceinline__ float2 unpack2(ull v) {
    float2 f;
    asm("mov.b64 {%0, %1}, %2;" : "=f"(f.x), "=f"(f.y) : "l"(v));
    return f;
}

// ---------------- detect dtype + zero counts + zero flags ----------------
__global__ void k_detect_zero(const unsigned int* __restrict__ w) {
    int i = blockIdx.x * 256 + threadIdx.x;
    if (i < NN) g_counts[i] = 0;
    if (blockIdx.x == 1 && threadIdx.x < 64) g_flagarr[threadIdx.x] = 0;
    if (blockIdx.x == 0) {
        __shared__ int cnt;
        if (threadIdx.x == 0) cnt = 0;
        __syncthreads();
        int z = 0;
        for (int k = threadIdx.x; k < 1024; k += 256)
            if (w[2 * k + 1] == 0u) z++;
        atomicAdd(&cnt, z);
        __syncthreads();
        if (threadIdx.x == 0) g_is64 = (cnt > 512) ? 1 : 0;
    }
}

__device__ __forceinline__ int load_idx(const void* ei, long pos) {
    return g_is64 ? (int)((const long long*)ei)[pos] : ((const int*)ei)[pos];
}

// ---------------- CSR build (2 edges/thread for atomic MLP) ----------------
__global__ void k_hist(const void* __restrict__ ei) {
    int e = (blockIdx.x * blockDim.x + threadIdx.x) * 2;
    if (e < EE) {
        int d0 = load_idx(ei, (long)EE + e);
        int d1 = (e + 1 < EE) ? load_idx(ei, (long)EE + e + 1) : -1;
        atomicAdd(&g_counts[d0], 1);
        if (d1 >= 0) atomicAdd(&g_counts[d1], 1);
    }
}

// single-kernel scan: per-block scan + decoupled aggregate exchange.
__global__ void k_scan_fused() {
    __shared__ int wsum[32];
    __shared__ int s_total, s_off;
    int bid = blockIdx.x;
    int i = bid * 1024 + threadIdx.x;
    int lane = threadIdx.x & 31, wid = threadIdx.x >> 5;
    int v = (i < NN) ? g_counts[i] : 0;
    int incl = v;
#pragma unroll
    for (int o = 1; o < 32; o <<= 1) {
        int xx = __shfl_up_sync(0xffffffffu, incl, o);
        if (lane >= o) incl += xx;
    }
    if (lane == 31) wsum[wid] = incl;
    __syncthreads();
    if (wid == 0) {
        int ws = wsum[lane];
        int wincl = ws;
#pragma unroll
        for (int o = 1; o < 32; o <<= 1) {
            int xx = __shfl_up_sync(0xffffffffu, wincl, o);
            if (lane >= o) wincl += xx;
        }
        wsum[lane] = wincl - ws;
        if (lane == 31) s_total = wincl;
    }
    __syncthreads();
    int excl = wsum[wid] + incl - v;

    if (threadIdx.x == 0) {
        g_blksum[bid] = s_total;
        __threadfence();
        atomicExch(&g_flagarr[bid], 1);
    }
    if (wid == 0) {
        int sum = 0;
        for (int p = lane; p < bid; p += 32) {
            while (atomicAdd(&g_flagarr[p], 0) == 0) {}
            sum += g_blksum[p];
        }
#pragma unroll
        for (int o = 16; o > 0; o >>= 1)
            sum += __shfl_xor_sync(0xffffffffu, sum, o);
        if (lane == 0) s_off = sum;
    }
    __syncthreads();
    if (i < NN) {
        int r = excl + s_off;
        g_rowptr[i] = r;
        g_next[i] = r;
    }
    if (bid == 0 && threadIdx.x == 0) g_rowptr[NN] = EE;
}

__global__ void k_scatter(const void* __restrict__ ei) {
    int e = (blockIdx.x * blockDim.x + threadIdx.x) * 2;
    if (e < EE) {
        int dn0 = load_idx(ei, (long)EE + e);
        int sn0 = load_idx(ei, e);
        bool two = (e + 1 < EE);
        int dn1 = two ? load_idx(ei, (long)EE + e + 1) : 0;
        int sn1 = two ? load_idx(ei, e + 1) : 0;
        int p0 = atomicAdd(&g_next[dn0], 1);
        int p1 = two ? atomicAdd(&g_next[dn1], 1) : 0;
        g_src[p0] = sn0;
        if (two) g_src[p1] = sn1;
    }
}

// ---------------- dual GEMM (best measured config: 80.9us) ----------------
template <bool USE_H>
__global__ void __launch_bounds__(512, 1)
k_dual_gemm(const float* __restrict__ A_param,
            const float* __restrict__ W1, const float* __restrict__ W2) {
    const float* A = USE_H ? (const float*)g_h : A_param;
    __shared__ float As[32][128];
    __shared__ float Ws[32][256];
    int t = threadIdx.x;
    int row0 = blockIdx.x * 128;
    int rt = t >> 5, ct = t & 31;

    int ar0 = t >> 3, ac0 = t & 7;
    int ar1 = (t + 512) >> 3, ac1 = (t + 512) & 7;
    int gr0 = row0 + ar0, gr1 = row0 + ar1;

    ull acc2[8][4];
#pragma unroll
    for (int i = 0; i < 8; i++)
#pragma unroll
        for (int j = 0; j < 4; j++) acc2[i][j] = 0ull;

    float4 aT[2], wT[4];
    aT[0] = (gr0 < NN) ? *(const float4*)(A + (long)gr0 * FDIM + ac0 * 4)
                       : make_float4(0.f, 0.f, 0.f, 0.f);
    aT[1] = (gr1 < NN) ? *(const float4*)(A + (long)gr1 * FDIM + ac1 * 4)
                       : make_float4(0.f, 0.f, 0.f, 0.f);
#pragma unroll
    for (int i = 0; i < 4; i++) {
        int idx = t + i * 512;
        int k = idx >> 6, c4 = idx & 63;
        wT[i] = (c4 < 32) ? *(const float4*)(W1 + k * FDIM + c4 * 4)
                          : *(const float4*)(W2 + k * FDIM + (c4 - 32) * 4);
    }

    for (int kc = 0; kc < 128; kc += 32) {
        As[ac0 * 4 + 0][ar0] = aT[0].x;
        As[ac0 * 4 + 1][ar0] = aT[0].y;
        As[ac0 * 4 + 2][ar0] = aT[0].z;
        As[ac0 * 4 + 3][ar0] = aT[0].w;
        As[ac1 * 4 + 0][ar1] = aT[1].x;
        As[ac1 * 4 + 1][ar1] = aT[1].y;
        As[ac1 * 4 + 2][ar1] = aT[1].z;
        As[ac1 * 4 + 3][ar1] = aT[1].w;
#pragma unroll
        for (int i = 0; i < 4; i++) {
            int idx = t + i * 512;
            int k = idx >> 6, c4 = idx & 63;
            *(float4*)(&Ws[k][c4 * 4]) = wT[i];
        }
        __syncthreads();

        int kn = kc + 32;
        if (kn < 128) {
            aT[0] = (gr0 < NN) ? *(const float4*)(A + (long)gr0 * FDIM + kn + ac0 * 4)
                               : make_float4(0.f, 0.f, 0.f, 0.f);
            aT[1] = (gr1 < NN) ? *(const float4*)(A + (long)gr1 * FDIM + kn + ac1 * 4)
                               : make_float4(0.f, 0.f, 0.f, 0.f);
#pragma unroll
            for (int i = 0; i < 4; i++) {
                int idx = t + i * 512;
                int k = idx >> 6, c4 = idx & 63;
                wT[i] = (c4 < 32) ? *(const float4*)(W1 + (kn + k) * FDIM + c4 * 4)
                                  : *(const float4*)(W2 + (kn + k) * FDIM + (c4 - 32) * 4);
            }
        }

#pragma unroll 4
        for (int kk = 0; kk < 32; kk++) {
            float4 a0 = *(const float4*)(&As[kk][rt * 8]);
            float4 a1 = *(const float4*)(&As[kk][rt * 8 + 4]);
            ulonglong2 w01 = *(const ulonglong2*)(&Ws[kk][ct * 4]);
            ulonglong2 w23 = *(const ulonglong2*)(&Ws[kk][ct * 4 + 128]);
            float a[8] = {a0.x, a0.y, a0.z, a0.w, a1.x, a1.y, a1.z, a1.w};
#pragma unroll
            for (int i = 0; i < 8; i++) {
                ull ap = pack2(a[i], a[i]);
                fma2(acc2[i][0], ap, w01.x);
                fma2(acc2[i][1], ap, w01.y);
                fma2(acc2[i][2], ap, w23.x);
                fma2(acc2[i][3], ap, w23.y);
            }
        }
        __syncthreads();
    }

#pragma unroll
    for (int i = 0; i < 8; i++) {
        int gr = row0 + rt * 8 + i;
        if (gr < NN) {
            float2 p0 = unpack2(acc2[i][0]), p1 = unpack2(acc2[i][1]);
            float2 p2 = unpack2(acc2[i][2]), p3 = unpack2(acc2[i][3]);
            *(float4*)(g_xl + (long)gr * FDIM + ct * 4) =
                make_float4(p0.x, p0.y, p1.x, p1.y);
            *(float4*)(g_xr + (long)gr * FDIM + ct * 4) =
                make_float4(p2.x, p2.y, p3.x, p3.y);
        }
    }
}

// ---------------- fused per-node attention (online softmax), warp per node ----------------
__device__ __forceinline__ float lrelu(float v) { return v > 0.f ? v : 0.2f * v; }

template <int H>
__device__ __forceinline__ float edge_score(float4 xlv, float4 xrv, float4 av, int lane) {
    float p = lrelu(xlv.x + xrv.x) * av.x
            + lrelu(xlv.y + xrv.y) * av.y
            + lrelu(xlv.z + xrv.z) * av.z
            + lrelu(xlv.w + xrv.w) * av.w;
#pragma unroll
    for (int o = 1; o < 32 / H; o <<= 1)
        p += __shfl_xor_sync(0xffffffffu, p, o);
    return p;
}

template <int H, bool OUT_H>
__global__ void k_aggregate(const float* __restrict__ att, const float* __restrict__ bias,
                            float* __restrict__ out_param) {
    float* out = OUT_H ? (float*)g_h : out_param;
    int gw = (blockIdx.x * blockDim.x + threadIdx.x) >> 5;
    int lane = threadIdx.x & 31;
    if (gw >= NN) return;
    int n = gw;

    float4 xrv = *(const float4*)(g_xr + (long)n * FDIM + lane * 4);
    float4 av  = *(const float4*)(att + lane * 4);
    float4 bv  = *(const float4*)(bias + lane * 4);

    float4 x1 = *(const float4*)(g_xl + (long)n * FDIM + lane * 4);
    float m = edge_score<H>(x1, xrv, av, lane);
    float d = 1.f;
    float4 acc = x1;

    int j = g_rowptr[n], end = g_rowptr[n + 1];
    for (; j + 1 < end; j += 2) {
        int s1 = g_src[j], s2 = g_src[j + 1];
        x1 = *(const float4*)(g_xl + (long)s1 * FDIM + lane * 4);
        float4 x2 = *(const float4*)(g_xl + (long)s2 * FDIM + lane * 4);
        float p1 = edge_score<H>(x1, xrv, av, lane);
        float p2 = edge_score<H>(x2, xrv, av, lane);
        float pm = fmaxf(p1, p2);
        if (pm <= m) {
            float e1 = __expf(p1 - m), e2 = __expf(p2 - m);
            d += e1 + e2;
            acc.x = fmaf(e1, x1.x, fmaf(e2, x2.x, acc.x));
            acc.y = fmaf(e1, x1.y, fmaf(e2, x2.y, acc.y));
            acc.z = fmaf(e1, x1.z, fmaf(e2, x2.z, acc.z));
            acc.w = fmaf(e1, x1.w, fmaf(e2, x2.w, acc.w));
        } else {
            float sc = __expf(m - pm);
            float e1 = __expf(p1 - pm), e2 = __expf(p2 - pm);
            d = fmaf(d, sc, e1 + e2);
            acc.x = fmaf(acc.x, sc, fmaf(e1, x1.x, e2 * x2.x));
            acc.y = fmaf(acc.y, sc, fmaf(e1, x1.y, e2 * x2.y));
            acc.z = fmaf(acc.z, sc, fmaf(e1, x1.z, e2 * x2.z));
            acc.w = fmaf(acc.w, sc, fmaf(e1, x1.w, e2 * x2.w));
            m = pm;
        }
    }
    if (j < end) {
        int s1 = g_src[j];
        x1 = *(const float4*)(g_xl + (long)s1 * FDIM + lane * 4);
        float p1 = edge_score<H>(x1, xrv, av, lane);
        if (p1 <= m) {
            float e1 = __expf(p1 - m);
            d += e1;
            acc.x = fmaf(e1, x1.x, acc.x);
            acc.y = fmaf(e1, x1.y, acc.y);
            acc.z = fmaf(e1, x1.z, acc.z);
            acc.w = fmaf(e1, x1.w, acc.w);
        } else {
            float sc = __expf(m - p1);
            d = fmaf(d, sc, 1.f);
            acc.x = fmaf(acc.x, sc, x1.x);
            acc.y = fmaf(acc.y, sc, x1.y);
            acc.z = fmaf(acc.z, sc, x1.z);
            acc.w = fmaf(acc.w, sc, x1.w);
        }
    }
    float inv = 1.f / d;
    float4 o = make_float4(fmaf(acc.x, inv, bv.x), fmaf(acc.y, inv, bv.y),
                           fmaf(acc.z, inv, bv.z), fmaf(acc.w, inv, bv.w));
    *(float4*)(out + (long)n * FDIM + lane * 4) = o;
}

// ---------------- launch ----------------
extern "C" void kernel_launch(void* const* d_in, const int* in_sizes, int n_in,
                              void* d_out, int out_size) {
    const float* x    = (const float*)d_in[0];
    const void*  ei   = d_in[1];
    const float* Wl1  = (const float*)d_in[3];
    const float* Wr1  = (const float*)d_in[4];
    const float* att1 = (const float*)d_in[5];
    const float* b1   = (const float*)d_in[6];
    const float* Wl2  = (const float*)d_in[7];
    const float* Wr2  = (const float*)d_in[8];
    const float* att2 = (const float*)d_in[9];
    const float* b2   = (const float*)d_in[10];
    float* out = (float*)d_out;

    int gemm_blocks = (NN + 127) / 128;
    int agg_blocks = (NN + 7) / 8;
    cudaStream_t s2 = g_ss.s2;

    // fork: CSR chain on s2, concurrent with layer-1 GEMM on main stream
    cudaEventRecord(g_ss.e1, 0);
    cudaStreamWaitEvent(s2, g_ss.e1, 0);

    k_detect_zero<<<(NN + 255) / 256, 256, 0, s2>>>((const unsigned int*)ei);
    k_hist<<<(EE / 2 + 255) / 256, 256, 0, s2>>>(ei);
    k_scan_fused<<<NBLK, 1024, 0, s2>>>();
    k_scatter<<<(EE / 2 + 255) / 256, 256, 0, s2>>>(ei);
    cudaEventRecord(g_ss.e2, s2);

    k_dual_gemm<false><<<gemm_blocks, 512>>>(x, Wl1, Wr1);

    // join
    cudaStreamWaitEvent(0, g_ss.e2, 0);

    k_aggregate<2, true><<<agg_blocks, 256>>>(att1, b1, nullptr);
    k_dual_gemm<true><<<gemm_blocks, 512>>>(nullptr, Wl2, Wr2);
    k_aggregate<1, false><<<agg_blocks, 256>>>(att2, b2, out);
}